// round 17
// baseline (speedup 1.0000x reference)
#include <cuda_runtime.h>
#include <cuda_bf16.h>
#include <stdint.h>

// out = relu(x @ W^T + b)  [softmax attention weights sum to 1 => attention = identity]
// Base-arch (compute_103) tensor-core path: mma.sync.m16n8k16 bf16 + ldmatrix + cp.async.
// 3-way bf16 split for fp32-like accuracy: D = Xh*Wh + Xh*Wl + Xl*Wh.
//
// R14: X split fused into GEMM (LDG f32 -> convert -> STS, register-prefetched);
// only W keeps a tiny split pre-kernel. Single __syncthreads per k-iter
// (issue-after-barrier makes the barrier the WAR guard), 4-stage B pipeline.

#define MDIM 32768
#define KDIM 256
#define NDIM 256

// -------- device scratch for split W (no allocation) --------
__device__ __nv_bfloat16 g_Wh[NDIM * KDIM];
__device__ __nv_bfloat16 g_Wl[NDIM * KDIM];

// -------- helpers --------
__device__ __forceinline__ uint32_t smem_u32(const void* p) {
    uint32_t a;
    asm("{ .reg .u64 t; cvta.to.shared.u64 t, %1; cvt.u32.u64 %0, t; }" : "=r"(a) : "l"(p));
    return a;
}
// pack: lower half = bf16(f0), upper half = bf16(f1)  (memory order f0,f1)
__device__ __forceinline__ uint32_t pack2(float f0, float f1) {
    uint32_t r;
    asm("cvt.rn.bf16x2.f32 %0, %1, %2;" : "=r"(r) : "f"(f1), "f"(f0));
    return r;
}
__device__ __forceinline__ float u2f(uint32_t u) { return __uint_as_float(u); }

__device__ __forceinline__ void cp16(uint32_t dst, const void* src) {
    asm volatile("cp.async.cg.shared.global [%0], [%1], 16;" :: "r"(dst), "l"(src));
}
__device__ __forceinline__ void cp_commit() {
    asm volatile("cp.async.commit_group;" ::: "memory");
}
template <int N> __device__ __forceinline__ void cp_wait() {
    asm volatile("cp.async.wait_group %0;" :: "n"(N) : "memory");
}
__device__ __forceinline__ void ldm_x4(uint32_t* r, uint32_t addr) {
    asm volatile("ldmatrix.sync.aligned.m8n8.x4.shared.b16 {%0,%1,%2,%3}, [%4];"
                 : "=r"(r[0]), "=r"(r[1]), "=r"(r[2]), "=r"(r[3]) : "r"(addr));
}
__device__ __forceinline__ void mma16816(float* d, const uint32_t* a, const uint32_t* b) {
    asm volatile("mma.sync.aligned.m16n8k16.row.col.f32.bf16.bf16.f32 "
                 "{%0,%1,%2,%3}, {%4,%5,%6,%7}, {%8,%9}, {%0,%1,%2,%3};"
                 : "+f"(d[0]), "+f"(d[1]), "+f"(d[2]), "+f"(d[3])
                 : "r"(a[0]), "r"(a[1]), "r"(a[2]), "r"(a[3]), "r"(b[0]), "r"(b[1]));
}

// split 8 fp32 (two float4) -> 16B hi bf16 + 16B lo bf16
__device__ __forceinline__ void split8(float4 a, float4 b, uint32_t* hi, uint32_t* lo) {
    uint32_t h01 = pack2(a.x, a.y);
    uint32_t h23 = pack2(a.z, a.w);
    uint32_t h45 = pack2(b.x, b.y);
    uint32_t h67 = pack2(b.z, b.w);
    hi[0] = h01; hi[1] = h23; hi[2] = h45; hi[3] = h67;
    lo[0] = pack2(a.x - u2f(h01 << 16), a.y - u2f(h01 & 0xFFFF0000u));
    lo[1] = pack2(a.z - u2f(h23 << 16), a.w - u2f(h23 & 0xFFFF0000u));
    lo[2] = pack2(b.x - u2f(h45 << 16), b.y - u2f(h45 & 0xFFFF0000u));
    lo[3] = pack2(b.z - u2f(h67 << 16), b.w - u2f(h67 & 0xFFFF0000u));
}
__device__ __forceinline__ void sts128(uint32_t addr, const uint32_t* v) {
    asm volatile("st.shared.v4.b32 [%0], {%1, %2, %3, %4};"
                 :: "r"(addr), "r"(v[0]), "r"(v[1]), "r"(v[2]), "r"(v[3]) : "memory");
}

// -------- kernel 1: split W fp32 -> (hi, lo) bf16 (tiny: 64 blocks) --------
__global__ __launch_bounds__(256)
void splitW_kernel(const float* __restrict__ W) {
    int j = blockIdx.x * 256 + threadIdx.x;        // 0..16383 float4s
    float4 v = ((const float4*)W)[j];
    uint32_t hi[4], lo[4];
    // reuse split8 layout: produces 4+4 packed words for 8 floats; here 4 floats -> 2+2
    uint32_t h01 = pack2(v.x, v.y);
    uint32_t h23 = pack2(v.z, v.w);
    float r0 = v.x - u2f(h01 << 16);
    float r1 = v.y - u2f(h01 & 0xFFFF0000u);
    float r2 = v.z - u2f(h23 << 16);
    float r3 = v.w - u2f(h23 & 0xFFFF0000u);
    ((uint2*)g_Wh)[j] = make_uint2(h01, h23);
    ((uint2*)g_Wl)[j] = make_uint2(pack2(r0, r1), pack2(r2, r3));
    (void)hi; (void)lo;
}

// -------- kernel 2: fused split-X + bf16 split-3 GEMM + bias + relu --------
// CTA tile 128x128, BK=32. A: 2-stage smem (reg-prefetched f32 -> convert -> STS).
// B: 4-stage cp.async from g_Wh/g_Wl (L2-resident).
// Rows are 64B (32 bf16) = 4 x 16B chunks; chunk swizzle: phys_c = c ^ (row & 3).
#define BK 32
#define KITERS (KDIM / BK)        // 8
#define BIAS_BYTES 1024
#define A_STAGE_BYTES 16384       // AH 8K + AL 8K
#define B_STAGE_BYTES 16384       // BH 8K + BL 8K
#define A_BASE BIAS_BYTES                         // 2 stages: [1024, 33792)
#define B_BASE (A_BASE + 2 * A_STAGE_BYTES)       // 4 stages: [33792, 99328)
#define SMEM_TOTAL (B_BASE + 4 * B_STAGE_BYTES)   // 99328

__global__ __launch_bounds__(256, 2)
void gemm_fused(const float* __restrict__ X, const float* __restrict__ bias,
                float* __restrict__ out) {
    extern __shared__ char smem[];
    const uint32_t sb = smem_u32(smem);
    const int tid = threadIdx.x;
    const int lane = tid & 31;
    const int wid = tid >> 5;
    const int wm = wid & 3;          // warp m index (32 rows each)
    const int wn = wid >> 2;         // warp n index (64 cols each)
    const int m0 = blockIdx.x * 128;
    const int n0 = blockIdx.y * 128;

    const int g = lane >> 2;
    const int tig = lane & 3;
    const int asub = lane >> 3;

    // bias -> smem
    if (tid < 128) ((float*)smem)[tid] = bias[n0 + tid];

    // A-conversion roles: thread covers row = tid>>1, k-half = tid&1 (16 floats)
    const int arow = tid >> 1;
    const int khalf = tid & 1;
    const float* xrow = X + (size_t)(m0 + arow) * KDIM + khalf * 16;

    // ldmatrix address roles
    const int a_row_base = wm * 32 + (asub & 1) * 8 + (lane & 7); // + mt*16
    const int a_cadd = asub >> 1;                                  // + ks*2
    const int b_row_base = wn * 64 + (asub >> 1) * 8 + (lane & 7); // + ntp*16
    const int b_cadd = asub & 1;                                   // + ks*2

    // B cp.async roles: 4 chunks/thread (2 BH + 2 BL share chunk ids)
    // chunk f (0..511): row = f>>2, c = f&3
    float acc[2][8][4];
#pragma unroll
    for (int i = 0; i < 2; i++)
#pragma unroll
        for (int j = 0; j < 8; j++)
#pragma unroll
            for (int q = 0; q < 4; q++) acc[i][j][q] = 0.0f;

    // ---- prologue: issue B stages 0..2, prefetch X iter 0 ----
#pragma unroll
    for (int s = 0; s < 3; s++) {
        uint32_t base = sb + B_BASE + (uint32_t)s * B_STAGE_BYTES;
        int kbase = s * BK;
#pragma unroll
        for (int h = 0; h < 2; h++) {
            int f = tid + h * 256;
            int row = f >> 2, c = f & 3;
            uint32_t sw = (uint32_t)row * 64 + ((uint32_t)(c ^ (row & 3)) << 4);
            size_t boff = (size_t)(n0 + row) * KDIM + kbase + c * 8;
            cp16(base + sw, g_Wh + boff);           // BH
            cp16(base + 8192 + sw, g_Wl + boff);    // BL
        }
        cp_commit();
    }
    float4 xa[4];
#pragma unroll
    for (int j = 0; j < 4; j++) xa[j] = *(const float4*)(xrow + j * 4);

    for (int it = 0; it < KITERS; it++) {
        // ---- convert prefetched X -> STS into A stage it&1 ----
        {
            uint32_t abase = sb + A_BASE + (uint32_t)(it & 1) * A_STAGE_BYTES;
            uint32_t hi[4], lo[4];
#pragma unroll
            for (int gch = 0; gch < 2; gch++) {
                split8(xa[2 * gch], xa[2 * gch + 1], hi, lo);
                int c = khalf * 2 + gch;
                uint32_t sw = (uint32_t)arow * 64 + ((uint32_t)(c ^ (arow & 3)) << 4);
                sts128(abase + sw, hi);            // AH
                sts128(abase + 8192 + sw, lo);     // AL
            }
        }
        cp_wait<2>();
        __syncthreads();

        // ---- issue B stage it+3 (after barrier => barrier is the WAR guard) ----
        if (it + 3 < KITERS) {
            uint32_t base = sb + B_BASE + (uint32_t)((it + 3) & 3) * B_STAGE_BYTES;
            int kbase = (it + 3) * BK;
#pragma unroll
            for (int h = 0; h < 2; h++) {
                int f = tid + h * 256;
                int row = f >> 2, c = f & 3;
                uint32_t sw = (uint32_t)row * 64 + ((uint32_t)(c ^ (row & 3)) << 4);
                size_t boff = (size_t)(n0 + row) * KDIM + kbase + c * 8;
                cp16(base + sw, g_Wh + boff);
                cp16(base + 8192 + sw, g_Wl + boff);
            }
        }
        cp_commit();

        // ---- prefetch X for next iter (lands during MMA phase) ----
        if (it + 1 < KITERS) {
            const float* xp = xrow + (it + 1) * BK;
#pragma unroll
            for (int j = 0; j < 4; j++) xa[j] = *(const float4*)(xp + j * 4);
        }

        // ---- compute ----
        uint32_t abase = sb + A_BASE + (uint32_t)(it & 1) * A_STAGE_BYTES;
        uint32_t bbase = sb + B_BASE + (uint32_t)(it & 3) * B_STAGE_BYTES;
#pragma unroll
        for (int ks = 0; ks < 2; ks++) {
            uint32_t aH[2][4], aL[2][4], bH[4][4], bL[4][4];
#pragma unroll
            for (int mt = 0; mt < 2; mt++) {
                int row = a_row_base + mt * 16;
                int c = ks * 2 + a_cadd;
                uint32_t sw = (uint32_t)row * 64 + ((uint32_t)(c ^ (row & 3)) << 4);
                ldm_x4(aH[mt], abase + sw);
                ldm_x4(aL[mt], abase + 8192 + sw);
            }
#pragma unroll
            for (int ntp = 0; ntp < 4; ntp++) {
                int row = b_row_base + ntp * 16;
                int c = ks * 2 + b_cadd;
                uint32_t sw = (uint32_t)row * 64 + ((uint32_t)(c ^ (row & 3)) << 4);
                ldm_x4(bH[ntp], bbase + sw);
                ldm_x4(bL[ntp], bbase + 8192 + sw);
            }
#pragma unroll
            for (int mt = 0; mt < 2; mt++)
#pragma unroll
                for (int ntp = 0; ntp < 4; ntp++)
#pragma unroll
                    for (int hf = 0; hf < 2; hf++) {
                        float* d = acc[mt][ntp * 2 + hf];
                        mma16816(d, aH[mt], &bH[ntp][hf * 2]);   // Xh*Wh
                        mma16816(d, aH[mt], &bL[ntp][hf * 2]);   // Xh*Wl
                        mma16816(d, aL[mt], &bH[ntp][hf * 2]);   // Xl*Wh
                    }
        }
        __syncthreads();   // A-stage WAR guard (2-stage A: reuse at it+2)
    }

    // ---- epilogue: bias + relu, float2 stores ----
    const float* sbias = (const float*)smem;
#pragma unroll
    for (int mt = 0; mt < 2; mt++) {
        int row = m0 + wm * 32 + mt * 16 + g;
#pragma unroll
        for (int nt = 0; nt < 8; nt++) {
            int lcol = wn * 64 + nt * 8 + 2 * tig;
            int col = n0 + lcol;
            float b0 = sbias[lcol], b1 = sbias[lcol + 1];
            const float* d = acc[mt][nt];
            float2 o0, o1;
            o0.x = fmaxf(d[0] + b0, 0.0f);
            o0.y = fmaxf(d[1] + b1, 0.0f);
            o1.x = fmaxf(d[2] + b0, 0.0f);
            o1.y = fmaxf(d[3] + b1, 0.0f);
            *(float2*)(out + (size_t)row * NDIM + col) = o0;
            *(float2*)(out + (size_t)(row + 8) * NDIM + col) = o1;
        }
    }
}

extern "C" void kernel_launch(void* const* d_in, const int* in_sizes, int n_in,
                              void* d_out, int out_size) {
    const float* x    = (const float*)d_in[0];   // [64,512,256]
    const float* W_w  = (const float*)d_in[1];   // [256,256]
    const float* W_b  = (const float*)d_in[2];   // [256]
    float* out = (float*)d_out;                  // [64,512,256]

    splitW_kernel<<<NDIM * KDIM / 4 / 256, 256>>>(W_w);   // 64 blocks

    static bool configured = false;
    if (!configured) {
        cudaFuncSetAttribute(gemm_fused,
                             cudaFuncAttributeMaxDynamicSharedMemorySize, SMEM_TOTAL);
        configured = true;
    }
    dim3 grid(MDIM / 128, NDIM / 128);           // (256, 2)
    gemm_fused<<<grid, 256, SMEM_TOTAL>>>(x, W_b, out);
}